// round 6
// baseline (speedup 1.0000x reference)
#include <cuda_runtime.h>
#include <cuda_bf16.h>
#include <math.h>

#define N_NODES 100000
#define IN_C 128
#define HID_C 128
#define OUT_C 64
#define N_EDGES 1600000

// ---------------- scratch (device globals: no allocations allowed) ----------
__device__ __align__(16) float g_deg[N_NODES];
__device__ __align__(16) float g_dinv[N_NODES];
__device__ __align__(16) float g_h1[(size_t)N_NODES * HID_C];   // x @ W1 (raw)
__device__ __align__(16) float g_a1[(size_t)N_NODES * HID_C];   // layer-1 accumulator
__device__ __align__(16) float g_h2[(size_t)N_NODES * OUT_C];   // relu(a1) @ W2 (raw)
__device__ __align__(16) float g_a2[(size_t)N_NODES * OUT_C];   // layer-2 accumulator
__device__ __align__(16) int   g_row[N_EDGES];
__device__ __align__(16) int   g_col[N_EDGES];
__device__ __align__(16) float g_norm[N_EDGES];
__device__ int g_is64;

// ---------------- edge-index normalization -----------------------------------
// Detect whether edge_index arrived as int64 or int32. Indices < 2^17, so in
// an int64 little-endian layout every odd 32-bit word is 0; in int32 layout
// those words are random indices (all-zero probability ~0).
__global__ void detect_kernel(const unsigned int* __restrict__ ei32) {
    int is64 = 1;
    for (int i = 1; i < 128; i += 2)
        if (ei32[i] != 0u) { is64 = 0; break; }
    g_is64 = is64;
}

__global__ void convert_kernel(const void* __restrict__ ei) {
    int e = blockIdx.x * blockDim.x + threadIdx.x;
    if (e >= N_EDGES) return;
    int r, c;
    if (g_is64) {
        const long long* p = (const long long*)ei;
        r = (int)p[e];
        c = (int)p[N_EDGES + e];
    } else {
        const int* p = (const int*)ei;
        r = p[e];
        c = p[N_EDGES + e];
    }
    // clamp defensively: valid data is untouched; bad data degrades to a
    // finite rel_err instead of a device trap.
    r = min(max(r, 0), N_NODES - 1);
    c = min(max(c, 0), N_NODES - 1);
    g_row[e] = r;
    g_col[e] = c;
}

// ---------------- degree / dinv / norm ---------------------------------------
__global__ void zero_deg_kernel() {
    int i = blockIdx.x * blockDim.x + threadIdx.x;
    if (i < N_NODES) g_deg[i] = 0.0f;
}

__global__ void degree_kernel() {
    int e = blockIdx.x * blockDim.x + threadIdx.x;
    if (e < N_EDGES) atomicAdd(&g_deg[g_col[e]], 1.0f);
}

__global__ void dinv_kernel() {
    int i = blockIdx.x * blockDim.x + threadIdx.x;
    if (i < N_NODES) g_dinv[i] = rsqrtf(g_deg[i] + 1.0f);
}

__global__ void norm_kernel() {
    int e = blockIdx.x * blockDim.x + threadIdx.x;
    if (e < N_EDGES) g_norm[e] = g_dinv[g_row[e]] * g_dinv[g_col[e]];
}

// ---------------- fused GEMM + self-loop epilogue ----------------------------
// LAYER==1: H1 = x @ W1 ; A1 = H1*dinv^2 + b1          (input = x param)
// LAYER==2: H2 = relu(A1) @ W2 ; A2 = H2*dinv^2 + b2   (input = g_a1 global)
// Static smem, K-chunked (KSTEP=32). 256 threads, 64-node tile.
template <int LAYER>
__global__ __launch_bounds__(256) void gemm_kernel(
    const float* __restrict__ X,       // used only for LAYER==1
    const float* __restrict__ W,
    const float* __restrict__ bias)
{
    constexpr int FIN   = 128;
    constexpr int FOUT  = (LAYER == 1) ? HID_C : OUT_C;
    constexpr int NTILE = 64;
    constexpr int KSTEP = 32;
    constexpr int CH    = (FOUT * NTILE) / (256 * 4);  // channels per thread (8 / 4)
    constexpr int PITCH = NTILE + 1;                   // 65: conflict-free stage writes

    __shared__ float sW[KSTEP * FOUT];
    __shared__ float sXT[KSTEP * PITCH];

    const int tid = threadIdx.x;
    const int n0  = blockIdx.x * NTILE;

    const int cg = tid % (FOUT / CH);
    const int ng = tid / (FOUT / CH);
    const int j0 = cg * CH;
    const int m0 = ng * 4;

    float acc[4][CH];
    #pragma unroll
    for (int a = 0; a < 4; a++)
        #pragma unroll
        for (int b = 0; b < CH; b++) acc[a][b] = 0.0f;

    for (int k0 = 0; k0 < FIN; k0 += KSTEP) {
        __syncthreads();
        {
            const float4* W4  = (const float4*)(W + (size_t)k0 * FOUT);
            float4*       sW4 = (float4*)sW;
            constexpr int CNT = KSTEP * FOUT / 4;
            #pragma unroll
            for (int i = tid; i < CNT; i += 256) sW4[i] = W4[i];
        }
        {
            constexpr int CNT = KSTEP * NTILE;
            #pragma unroll
            for (int i = tid; i < CNT; i += 256) {
                int k = i % KSTEP;
                int m = i / KSTEP;
                int n = n0 + m;
                float v = 0.0f;
                if (n < N_NODES) {
                    if (LAYER == 1) {
                        v = X[(size_t)n * FIN + k0 + k];
                    } else {
                        v = fmaxf(g_a1[(size_t)n * FIN + k0 + k], 0.0f);
                    }
                }
                sXT[k * PITCH + m] = v;
            }
        }
        __syncthreads();

        #pragma unroll 8
        for (int k = 0; k < KSTEP; k++) {
            float wv[CH], xv[4];
            #pragma unroll
            for (int j = 0; j < CH; j += 4) {
                float4 w4 = *(const float4*)&sW[k * FOUT + j0 + j];
                wv[j] = w4.x; wv[j + 1] = w4.y; wv[j + 2] = w4.z; wv[j + 3] = w4.w;
            }
            #pragma unroll
            for (int mi = 0; mi < 4; mi++) xv[mi] = sXT[k * PITCH + m0 + mi];
            #pragma unroll
            for (int mi = 0; mi < 4; mi++)
                #pragma unroll
                for (int j = 0; j < CH; j++)
                    acc[mi][j] = fmaf(xv[mi], wv[j], acc[mi][j]);
        }
    }

    float bv[CH];
    #pragma unroll
    for (int j = 0; j < CH; j++) bv[j] = bias[j0 + j];

    #pragma unroll
    for (int mi = 0; mi < 4; mi++) {
        int n = n0 + m0 + mi;
        if (n < N_NODES) {
            float di = g_dinv[n];
            float d2 = di * di;
            #pragma unroll
            for (int j = 0; j < CH; j += 4) {
                float4 hv = make_float4(acc[mi][j], acc[mi][j+1], acc[mi][j+2], acc[mi][j+3]);
                float4 av = make_float4(fmaf(hv.x, d2, bv[j]),   fmaf(hv.y, d2, bv[j+1]),
                                        fmaf(hv.z, d2, bv[j+2]), fmaf(hv.w, d2, bv[j+3]));
                if (LAYER == 1) {
                    *(float4*)&g_h1[(size_t)n * FOUT + j0 + j] = hv;
                    *(float4*)&g_a1[(size_t)n * FOUT + j0 + j] = av;
                } else {
                    *(float4*)&g_h2[(size_t)n * FOUT + j0 + j] = hv;
                    *(float4*)&g_a2[(size_t)n * FOUT + j0 + j] = av;
                }
            }
        }
    }
}

// ---------------- edge scatter: warp per edge, contiguous scalar REDs --------
__global__ __launch_bounds__(256) void scatter1_kernel() {
    int warp = (blockIdx.x * blockDim.x + threadIdx.x) >> 5;
    int lane = threadIdx.x & 31;
    if (warp >= N_EDGES) return;
    int r = g_row[warp];
    int c = g_col[warp];
    float norm = g_norm[warp];
    const float* src = g_h1 + (size_t)r * HID_C;
    float*       dst = g_a1 + (size_t)c * HID_C;
    #pragma unroll
    for (int i = 0; i < 4; i++) {
        int ch = lane + 32 * i;
        atomicAdd(dst + ch, src[ch] * norm);
    }
}

__global__ __launch_bounds__(256) void scatter2_kernel() {
    int warp = (blockIdx.x * blockDim.x + threadIdx.x) >> 5;
    int lane = threadIdx.x & 31;
    if (warp >= N_EDGES) return;
    int r = g_row[warp];
    int c = g_col[warp];
    float norm = g_norm[warp];
    const float* src = g_h2 + (size_t)r * OUT_C;
    float*       dst = g_a2 + (size_t)c * OUT_C;
    #pragma unroll
    for (int i = 0; i < 2; i++) {
        int ch = lane + 32 * i;
        atomicAdd(dst + ch, src[ch] * norm);
    }
}

// ---------------- final copy: plain STG into harness d_out -------------------
__global__ __launch_bounds__(256) void copy_out_kernel(float* __restrict__ out) {
    constexpr size_t TOT4 = (size_t)N_NODES * OUT_C / 4;
    size_t i = (size_t)blockIdx.x * blockDim.x + threadIdx.x;
    size_t stride = (size_t)gridDim.x * blockDim.x;
    const float4* src4 = (const float4*)g_a2;
    float4*       dst4 = (float4*)out;
    for (size_t j = i; j < TOT4; j += stride) dst4[j] = src4[j];
}

// ---------------- launch ------------------------------------------------------
extern "C" void kernel_launch(void* const* d_in, const int* in_sizes, int n_in,
                              void* d_out, int out_size)
{
    // identify inputs by element count (ordering-proof; all counts distinct)
    const float* x  = nullptr; const void* ei = nullptr;
    const float* W1 = nullptr; const float* b1 = nullptr;
    const float* W2 = nullptr; const float* b2 = nullptr;
    for (int i = 0; i < n_in; i++) {
        switch (in_sizes[i]) {
            case N_NODES * IN_C:   x  = (const float*)d_in[i]; break;   // 12,800,000
            case 2 * N_EDGES:      ei = d_in[i];               break;   // 3,200,000
            case IN_C * HID_C:     W1 = (const float*)d_in[i]; break;   // 16,384
            case HID_C:            b1 = (const float*)d_in[i]; break;   // 128
            case HID_C * OUT_C:    W2 = (const float*)d_in[i]; break;   // 8,192
            case OUT_C:            b2 = (const float*)d_in[i]; break;   // 64
            default: break;
        }
    }
    float* out = (float*)d_out;

    // normalize edge indices (dtype-agnostic), degree, dinv, per-edge norm
    detect_kernel<<<1, 1>>>((const unsigned int*)ei);
    convert_kernel<<<(N_EDGES + 255) / 256, 256>>>(ei);
    zero_deg_kernel<<<(N_NODES + 255) / 256, 256>>>();
    degree_kernel<<<(N_EDGES + 255) / 256, 256>>>();
    dinv_kernel<<<(N_NODES + 255) / 256, 256>>>();
    norm_kernel<<<(N_EDGES + 255) / 256, 256>>>();

    // layer 1
    gemm_kernel<1><<<(N_NODES + 63) / 64, 256>>>(x, W1, b1);
    scatter1_kernel<<<(int)(((long long)N_EDGES * 32 + 255) / 256), 256>>>();

    // layer 2
    gemm_kernel<2><<<(N_NODES + 63) / 64, 256>>>(nullptr, W2, b2);
    scatter2_kernel<<<(int)(((long long)N_EDGES * 32 + 255) / 256), 256>>>();

    // write result to harness output with plain stores
    copy_out_kernel<<<2048, 256>>>(out);
}

// round 7
// speedup vs baseline: 1.8089x; 1.8089x over previous
#include <cuda_runtime.h>
#include <cuda_bf16.h>
#include <math.h>

#define N_NODES 100000
#define IN_C 128
#define HID_C 128
#define OUT_C 64
#define N_EDGES 1600000

#define SCAN_BLK 512
#define NB1 ((N_NODES + SCAN_BLK - 1) / SCAN_BLK)   // 196

// ---------------- scratch (device globals: no allocations allowed) ----------
__device__ __align__(16) float g_dinv[N_NODES];
__device__ __align__(16) float g_h1[(size_t)N_NODES * HID_C];   // x @ W1 (raw)
__device__ __align__(16) float g_a1[(size_t)N_NODES * HID_C];   // layer-1 output (pre-relu)
__device__ __align__(16) float g_h2[(size_t)N_NODES * OUT_C];   // relu(a1) @ W2 (raw)
__device__ __align__(16) int   g_row[N_EDGES];
__device__ __align__(16) int   g_col[N_EDGES];
__device__ __align__(16) int   g_cnt[N_NODES];       // per-col degree (no self-loop)
__device__ __align__(16) int   g_incl[N_NODES];      // inclusive scan within block
__device__ __align__(16) int   g_part[256];          // block partial sums
__device__ __align__(16) int   g_partoff[256];       // exclusive block offsets
__device__ __align__(16) int   g_ptr[N_NODES + 1];   // CSR pointers (by col)
__device__ __align__(16) int   g_cur[N_NODES];       // fill cursors
__device__ __align__(16) int   g_csr[N_EDGES];       // source row per CSR slot
__device__ __align__(16) float g_csrw[N_EDGES];      // dinv[row] per CSR slot
__device__ int g_is64;

// ---------------- edge-index normalization -----------------------------------
// int64 vs int32 detection: indices < 2^17, so int64 layout has all odd 32-bit
// words zero; int32 layout has random indices there.
__global__ void detect_kernel(const unsigned int* __restrict__ ei32) {
    int is64 = 1;
    for (int i = 1; i < 128; i += 2)
        if (ei32[i] != 0u) { is64 = 0; break; }
    g_is64 = is64;
}

__global__ void convert_kernel(const void* __restrict__ ei) {
    int e = blockIdx.x * blockDim.x + threadIdx.x;
    if (e >= N_EDGES) return;
    int r, c;
    if (g_is64) {
        const long long* p = (const long long*)ei;
        r = (int)p[e];
        c = (int)p[N_EDGES + e];
    } else {
        const int* p = (const int*)ei;
        r = p[e];
        c = p[N_EDGES + e];
    }
    r = min(max(r, 0), N_NODES - 1);
    c = min(max(c, 0), N_NODES - 1);
    g_row[e] = r;
    g_col[e] = c;
}

// ---------------- histogram (degree) + prefix scan + CSR fill -----------------
__global__ void zero_cnt_kernel() {
    int i = blockIdx.x * blockDim.x + threadIdx.x;
    if (i < N_NODES) g_cnt[i] = 0;
}

__global__ void hist_kernel() {
    int e = blockIdx.x * blockDim.x + threadIdx.x;
    if (e < N_EDGES) atomicAdd(&g_cnt[g_col[e]], 1);
}

// inclusive scan within blocks of SCAN_BLK
__global__ __launch_bounds__(SCAN_BLK) void scan1_kernel() {
    __shared__ int s[SCAN_BLK];
    int t = threadIdx.x;
    int i = blockIdx.x * SCAN_BLK + t;
    int v = (i < N_NODES) ? g_cnt[i] : 0;
    s[t] = v;
    __syncthreads();
    for (int off = 1; off < SCAN_BLK; off <<= 1) {
        int add = (t >= off) ? s[t - off] : 0;
        __syncthreads();
        s[t] += add;
        __syncthreads();
    }
    if (i < N_NODES) g_incl[i] = s[t];
    if (t == SCAN_BLK - 1) g_part[blockIdx.x] = s[t];
}

// single block scans the partials -> exclusive block offsets
__global__ __launch_bounds__(256) void scan2_kernel() {
    __shared__ int s[256];
    int t = threadIdx.x;
    int v = (t < NB1) ? g_part[t] : 0;
    s[t] = v;
    __syncthreads();
    for (int off = 1; off < 256; off <<= 1) {
        int add = (t >= off) ? s[t - off] : 0;
        __syncthreads();
        s[t] += add;
        __syncthreads();
    }
    g_partoff[t] = s[t] - v;   // exclusive
}

// finalize: CSR ptr (exclusive), fill cursor, dinv
__global__ void scan3_kernel() {
    int i = blockIdx.x * blockDim.x + threadIdx.x;
    if (i >= N_NODES) return;
    int cnt  = g_cnt[i];
    int excl = g_partoff[i / SCAN_BLK] + g_incl[i] - cnt;
    g_ptr[i] = excl;
    g_cur[i] = excl;
    g_dinv[i] = rsqrtf((float)cnt + 1.0f);
    if (i == 0) g_ptr[N_NODES] = N_EDGES;
}

__global__ void csr_fill_kernel() {
    int e = blockIdx.x * blockDim.x + threadIdx.x;
    if (e >= N_EDGES) return;
    int r = g_row[e];
    int c = g_col[e];
    int pos = atomicAdd(&g_cur[c], 1);
    g_csr[pos]  = r;
    g_csrw[pos] = g_dinv[r];
}

// ---------------- GEMM: H = (relu?)X @ W -------------------------------------
// Static smem, K-chunked (KSTEP=32). 256 threads, 64-node tile. Writes H only.
template <int LAYER>
__global__ __launch_bounds__(256) void gemm_kernel(
    const float* __restrict__ X,       // used only for LAYER==1
    const float* __restrict__ W)
{
    constexpr int FIN   = 128;
    constexpr int FOUT  = (LAYER == 1) ? HID_C : OUT_C;
    constexpr int NTILE = 64;
    constexpr int KSTEP = 32;
    constexpr int CH    = (FOUT * NTILE) / (256 * 4);  // 8 / 4
    constexpr int PITCH = NTILE + 1;

    __shared__ float sW[KSTEP * FOUT];
    __shared__ float sXT[KSTEP * PITCH];

    const int tid = threadIdx.x;
    const int n0  = blockIdx.x * NTILE;

    const int cg = tid % (FOUT / CH);
    const int ng = tid / (FOUT / CH);
    const int j0 = cg * CH;
    const int m0 = ng * 4;

    float acc[4][CH];
    #pragma unroll
    for (int a = 0; a < 4; a++)
        #pragma unroll
        for (int b = 0; b < CH; b++) acc[a][b] = 0.0f;

    for (int k0 = 0; k0 < FIN; k0 += KSTEP) {
        __syncthreads();
        {
            const float4* W4  = (const float4*)(W + (size_t)k0 * FOUT);
            float4*       sW4 = (float4*)sW;
            constexpr int CNT = KSTEP * FOUT / 4;
            #pragma unroll
            for (int i = tid; i < CNT; i += 256) sW4[i] = W4[i];
        }
        {
            constexpr int CNT = KSTEP * NTILE;
            #pragma unroll
            for (int i = tid; i < CNT; i += 256) {
                int k = i % KSTEP;
                int m = i / KSTEP;
                int n = n0 + m;
                float v = 0.0f;
                if (n < N_NODES) {
                    if (LAYER == 1) {
                        v = X[(size_t)n * FIN + k0 + k];
                    } else {
                        v = fmaxf(g_a1[(size_t)n * FIN + k0 + k], 0.0f);
                    }
                }
                sXT[k * PITCH + m] = v;
            }
        }
        __syncthreads();

        #pragma unroll 8
        for (int k = 0; k < KSTEP; k++) {
            float wv[CH], xv[4];
            #pragma unroll
            for (int j = 0; j < CH; j += 4) {
                float4 w4 = *(const float4*)&sW[k * FOUT + j0 + j];
                wv[j] = w4.x; wv[j + 1] = w4.y; wv[j + 2] = w4.z; wv[j + 3] = w4.w;
            }
            #pragma unroll
            for (int mi = 0; mi < 4; mi++) xv[mi] = sXT[k * PITCH + m0 + mi];
            #pragma unroll
            for (int mi = 0; mi < 4; mi++)
                #pragma unroll
                for (int j = 0; j < CH; j++)
                    acc[mi][j] = fmaf(xv[mi], wv[j], acc[mi][j]);
        }
    }

    float* Hout = (LAYER == 1) ? g_h1 : g_h2;
    #pragma unroll
    for (int mi = 0; mi < 4; mi++) {
        int n = n0 + m0 + mi;
        if (n < N_NODES) {
            #pragma unroll
            for (int j = 0; j < CH; j += 4) {
                float4 hv = make_float4(acc[mi][j], acc[mi][j+1], acc[mi][j+2], acc[mi][j+3]);
                *(float4*)&Hout[(size_t)n * FOUT + j0 + j] = hv;
            }
        }
    }
}

// ---------------- CSR gather: one block per destination node ------------------
// agg[c] = dinv[c] * sum_j dinv[r_j] * H[r_j]  +  dinv[c]^2 * H[c]  +  bias
// Neighbor slots staged coalesced into smem; inner loop reads are 128B/warp
// contiguous LDGs from the L2-resident H array. Single write per node.
template <int FOUT>
__global__ __launch_bounds__(FOUT) void gather_kernel(
    const float* __restrict__ H,
    const float* __restrict__ bias,
    float* __restrict__ Aout)
{
    __shared__ int   s_r[FOUT];
    __shared__ float s_w[FOUT];

    const int n  = blockIdx.x;
    const int ch = threadIdx.x;

    const int beg = g_ptr[n];
    const int end = g_ptr[n + 1];
    const float dc = g_dinv[n];

    float acc = 0.0f;
    for (int base = beg; base < end; base += FOUT) {
        int j = base + ch;
        if (j < end) {
            s_r[ch] = g_csr[j];
            s_w[ch] = g_csrw[j];
        }
        __syncthreads();
        int cnt = min(FOUT, end - base);
        int i = 0;
        for (; i + 4 <= cnt; i += 4) {
            float v0 = H[(size_t)s_r[i]     * FOUT + ch];
            float v1 = H[(size_t)s_r[i + 1] * FOUT + ch];
            float v2 = H[(size_t)s_r[i + 2] * FOUT + ch];
            float v3 = H[(size_t)s_r[i + 3] * FOUT + ch];
            acc = fmaf(s_w[i],     v0, acc);
            acc = fmaf(s_w[i + 1], v1, acc);
            acc = fmaf(s_w[i + 2], v2, acc);
            acc = fmaf(s_w[i + 3], v3, acc);
        }
        for (; i < cnt; i++)
            acc = fmaf(s_w[i], H[(size_t)s_r[i] * FOUT + ch], acc);
        __syncthreads();
    }

    float self = H[(size_t)n * FOUT + ch];
    Aout[(size_t)n * FOUT + ch] = fmaf(dc, acc, fmaf(dc * dc, self, bias[ch]));
}

// ---------------- launch ------------------------------------------------------
extern "C" void kernel_launch(void* const* d_in, const int* in_sizes, int n_in,
                              void* d_out, int out_size)
{
    // identify inputs by element count (ordering-proof; all counts distinct)
    const float* x  = nullptr; const void* ei = nullptr;
    const float* W1 = nullptr; const float* b1 = nullptr;
    const float* W2 = nullptr; const float* b2 = nullptr;
    for (int i = 0; i < n_in; i++) {
        switch (in_sizes[i]) {
            case N_NODES * IN_C:   x  = (const float*)d_in[i]; break;
            case 2 * N_EDGES:      ei = d_in[i];               break;
            case IN_C * HID_C:     W1 = (const float*)d_in[i]; break;
            case HID_C:            b1 = (const float*)d_in[i]; break;
            case HID_C * OUT_C:    W2 = (const float*)d_in[i]; break;
            case OUT_C:            b2 = (const float*)d_in[i]; break;
            default: break;
        }
    }
    float* out = (float*)d_out;

    // edge normalization + CSR build (histogram doubles as degree)
    detect_kernel<<<1, 1>>>((const unsigned int*)ei);
    convert_kernel<<<(N_EDGES + 255) / 256, 256>>>(ei);
    zero_cnt_kernel<<<(N_NODES + 255) / 256, 256>>>();
    hist_kernel<<<(N_EDGES + 255) / 256, 256>>>();
    scan1_kernel<<<NB1, SCAN_BLK>>>();
    scan2_kernel<<<1, 256>>>();
    scan3_kernel<<<(N_NODES + 255) / 256, 256>>>();
    csr_fill_kernel<<<(N_EDGES + 255) / 256, 256>>>();

    // layer 1: h1 = x@W1 ; a1 = gather(h1) + self + b1
    gemm_kernel<1><<<(N_NODES + 63) / 64, 256>>>(x, W1);
    float* p_a1; cudaGetSymbolAddress((void**)&p_a1, g_a1);
    float* p_h1; cudaGetSymbolAddress((void**)&p_h1, g_h1);
    gather_kernel<HID_C><<<N_NODES, HID_C>>>(p_h1, b1, p_a1);

    // layer 2: h2 = relu(a1)@W2 ; out = gather(h2) + self + b2 (direct to d_out)
    gemm_kernel<2><<<(N_NODES + 63) / 64, 256>>>(nullptr, W2);
    float* p_h2; cudaGetSymbolAddress((void**)&p_h2, g_h2);
    gather_kernel<OUT_C><<<N_NODES, OUT_C>>>(p_h2, b2, out);
}

// round 8
// speedup vs baseline: 1.9594x; 1.0832x over previous
#include <cuda_runtime.h>
#include <cuda_bf16.h>
#include <math.h>

#define N_NODES 100000
#define IN_C 128
#define HID_C 128
#define OUT_C 64
#define N_EDGES 1600000

#define SCAN_BLK 512
#define NB1 ((N_NODES + SCAN_BLK - 1) / SCAN_BLK)   // 196

// ---------------- scratch (device globals: no allocations allowed) ----------
__device__ __align__(16) float g_dinv[N_NODES];
__device__ __align__(16) float g_h1[(size_t)N_NODES * HID_C];   // x @ W1 (raw)
__device__ __align__(16) float g_a1[(size_t)N_NODES * HID_C];   // layer-1 output (pre-relu)
__device__ __align__(16) float g_h2[(size_t)N_NODES * OUT_C];   // relu(a1) @ W2 (raw)
__device__ __align__(16) int2  g_rc[N_EDGES];        // packed {row, col}
__device__ __align__(16) int2  g_csre[N_EDGES];      // packed {row, bits(dinv[row])}
__device__ __align__(16) int   g_cnt[N_NODES];       // per-col degree (no self-loop)
__device__ __align__(16) int   g_incl[N_NODES];      // inclusive scan within block
__device__ __align__(16) int   g_part[256];          // block partial sums
__device__ __align__(16) int   g_partoff[256];       // exclusive block offsets
__device__ __align__(16) int   g_ptr[N_NODES + 1];   // CSR pointers (by col)
__device__ __align__(16) int   g_cur[N_NODES];       // fill cursors
__device__ int g_is64;

// ---------------- f32x2 packed-FMA helpers ------------------------------------
__device__ __forceinline__ unsigned long long pack_dup(float x) {
    unsigned long long r;
    asm("mov.b64 %0, {%1, %1};" : "=l"(r) : "f"(x));
    return r;
}
__device__ __forceinline__ void fma2(unsigned long long& d,
                                     unsigned long long a, unsigned long long b) {
    asm("fma.rn.f32x2 %0, %1, %2, %0;" : "+l"(d) : "l"(a), "l"(b));
}
__device__ __forceinline__ void unpack2(unsigned long long v, float& lo, float& hi) {
    asm("mov.b64 {%0, %1}, %2;" : "=f"(lo), "=f"(hi) : "l"(v));
}

// ---------------- edge-index normalization + histogram ------------------------
// int64 vs int32 detection: indices < 2^17, so int64 layout has all odd 32-bit
// words zero; int32 layout has random indices there.
__global__ void detect_kernel(const unsigned int* __restrict__ ei32) {
    int is64 = 1;
    for (int i = 1; i < 128; i += 2)
        if (ei32[i] != 0u) { is64 = 0; break; }
    g_is64 = is64;
}

__global__ void zero_cnt_kernel() {
    int i = blockIdx.x * blockDim.x + threadIdx.x;
    if (i < N_NODES) g_cnt[i] = 0;
}

// fused: decode -> clamp -> store packed {r,c} -> degree histogram
__global__ void convert_hist_kernel(const void* __restrict__ ei) {
    int e = blockIdx.x * blockDim.x + threadIdx.x;
    if (e >= N_EDGES) return;
    int r, c;
    if (g_is64) {
        const long long* p = (const long long*)ei;
        r = (int)p[e];
        c = (int)p[N_EDGES + e];
    } else {
        const int* p = (const int*)ei;
        r = p[e];
        c = p[N_EDGES + e];
    }
    r = min(max(r, 0), N_NODES - 1);
    c = min(max(c, 0), N_NODES - 1);
    g_rc[e] = make_int2(r, c);
    atomicAdd(&g_cnt[c], 1);
}

// ---------------- prefix scan + CSR fill --------------------------------------
__global__ __launch_bounds__(SCAN_BLK) void scan1_kernel() {
    __shared__ int s[SCAN_BLK];
    int t = threadIdx.x;
    int i = blockIdx.x * SCAN_BLK + t;
    int v = (i < N_NODES) ? g_cnt[i] : 0;
    s[t] = v;
    __syncthreads();
    for (int off = 1; off < SCAN_BLK; off <<= 1) {
        int add = (t >= off) ? s[t - off] : 0;
        __syncthreads();
        s[t] += add;
        __syncthreads();
    }
    if (i < N_NODES) g_incl[i] = s[t];
    if (t == SCAN_BLK - 1) g_part[blockIdx.x] = s[t];
}

__global__ __launch_bounds__(256) void scan2_kernel() {
    __shared__ int s[256];
    int t = threadIdx.x;
    int v = (t < NB1) ? g_part[t] : 0;
    s[t] = v;
    __syncthreads();
    for (int off = 1; off < 256; off <<= 1) {
        int add = (t >= off) ? s[t - off] : 0;
        __syncthreads();
        s[t] += add;
        __syncthreads();
    }
    g_partoff[t] = s[t] - v;   // exclusive
}

__global__ void scan3_kernel() {
    int i = blockIdx.x * blockDim.x + threadIdx.x;
    if (i >= N_NODES) return;
    int cnt  = g_cnt[i];
    int excl = g_partoff[i / SCAN_BLK] + g_incl[i] - cnt;
    g_ptr[i] = excl;
    g_cur[i] = excl;
    g_dinv[i] = rsqrtf((float)cnt + 1.0f);
    if (i == 0) g_ptr[N_NODES] = N_EDGES;
}

__global__ void csr_fill_kernel() {
    int e = blockIdx.x * blockDim.x + threadIdx.x;
    if (e >= N_EDGES) return;
    int2 rc = g_rc[e];
    int pos = atomicAdd(&g_cur[rc.y], 1);
    g_csre[pos] = make_int2(rc.x, __float_as_int(g_dinv[rc.x]));
}

// ---------------- GEMM: H = (relu?)X @ W, f32x2 packed FMA --------------------
template <int LAYER>
__global__ __launch_bounds__(256) void gemm_kernel(
    const float* __restrict__ X,       // used only for LAYER==1
    const float* __restrict__ W)
{
    constexpr int FIN   = 128;
    constexpr int FOUT  = (LAYER == 1) ? HID_C : OUT_C;
    constexpr int NTILE = 64;
    constexpr int KSTEP = 32;
    constexpr int CH    = (FOUT * NTILE) / (256 * 4);  // 8 / 4
    constexpr int PAIRS = CH / 2;                      // 4 / 2
    constexpr int PITCH = NTILE + 1;

    __shared__ float sW[KSTEP * FOUT];
    __shared__ float sXT[KSTEP * PITCH];

    const int tid = threadIdx.x;
    const int n0  = blockIdx.x * NTILE;

    const int cg = tid % (FOUT / CH);
    const int ng = tid / (FOUT / CH);
    const int j0 = cg * CH;
    const int m0 = ng * 4;

    unsigned long long acc2[4][PAIRS];
    #pragma unroll
    for (int a = 0; a < 4; a++)
        #pragma unroll
        for (int b = 0; b < PAIRS; b++) acc2[a][b] = 0ULL;   // two packed +0.0f

    for (int k0 = 0; k0 < FIN; k0 += KSTEP) {
        __syncthreads();
        {
            const float4* W4  = (const float4*)(W + (size_t)k0 * FOUT);
            float4*       sW4 = (float4*)sW;
            constexpr int CNT = KSTEP * FOUT / 4;
            #pragma unroll
            for (int i = tid; i < CNT; i += 256) sW4[i] = W4[i];
        }
        {
            constexpr int CNT = KSTEP * NTILE;
            #pragma unroll
            for (int i = tid; i < CNT; i += 256) {
                int k = i % KSTEP;
                int m = i / KSTEP;
                int n = n0 + m;
                float v = 0.0f;
                if (n < N_NODES) {
                    if (LAYER == 1) {
                        v = X[(size_t)n * FIN + k0 + k];
                    } else {
                        v = fmaxf(g_a1[(size_t)n * FIN + k0 + k], 0.0f);
                    }
                }
                sXT[k * PITCH + m] = v;
            }
        }
        __syncthreads();

        #pragma unroll 8
        for (int k = 0; k < KSTEP; k++) {
            unsigned long long w2[PAIRS];
            #pragma unroll
            for (int p = 0; p < PAIRS; p++)
                w2[p] = *(const unsigned long long*)&sW[k * FOUT + j0 + 2 * p];
            unsigned long long xp[4];
            #pragma unroll
            for (int mi = 0; mi < 4; mi++)
                xp[mi] = pack_dup(sXT[k * PITCH + m0 + mi]);
            #pragma unroll
            for (int mi = 0; mi < 4; mi++)
                #pragma unroll
                for (int p = 0; p < PAIRS; p++)
                    fma2(acc2[mi][p], xp[mi], w2[p]);
        }
    }

    float* Hout = (LAYER == 1) ? g_h1 : g_h2;
    #pragma unroll
    for (int mi = 0; mi < 4; mi++) {
        int n = n0 + m0 + mi;
        if (n < N_NODES) {
            #pragma unroll
            for (int p = 0; p < PAIRS; p += 2) {
                float4 hv;
                unpack2(acc2[mi][p],     hv.x, hv.y);
                unpack2(acc2[mi][p + 1], hv.z, hv.w);
                *(float4*)&Hout[(size_t)n * FOUT + j0 + 2 * p] = hv;
            }
        }
    }
}

// ---------------- CSR gather: one block per destination node ------------------
// agg[c] = dinv[c] * sum_j dinv[r_j] * H[r_j]  +  dinv[c]^2 * H[c]  +  bias
template <int FOUT>
__global__ __launch_bounds__(FOUT) void gather_kernel(
    const float* __restrict__ H,
    const float* __restrict__ bias,
    float* __restrict__ Aout)
{
    __shared__ int   s_r[FOUT];
    __shared__ float s_w[FOUT];

    const int n  = blockIdx.x;
    const int ch = threadIdx.x;

    const int beg = g_ptr[n];
    const int end = g_ptr[n + 1];
    const float dc = g_dinv[n];

    float acc = 0.0f;
    for (int base = beg; base < end; base += FOUT) {
        int j = base + ch;
        if (j < end) {
            int2 v = g_csre[j];
            s_r[ch] = v.x;
            s_w[ch] = __int_as_float(v.y);
        }
        __syncthreads();
        int cnt = min(FOUT, end - base);
        int i = 0;
        for (; i + 8 <= cnt; i += 8) {
            float v0 = H[(size_t)s_r[i]     * FOUT + ch];
            float v1 = H[(size_t)s_r[i + 1] * FOUT + ch];
            float v2 = H[(size_t)s_r[i + 2] * FOUT + ch];
            float v3 = H[(size_t)s_r[i + 3] * FOUT + ch];
            float v4 = H[(size_t)s_r[i + 4] * FOUT + ch];
            float v5 = H[(size_t)s_r[i + 5] * FOUT + ch];
            float v6 = H[(size_t)s_r[i + 6] * FOUT + ch];
            float v7 = H[(size_t)s_r[i + 7] * FOUT + ch];
            acc = fmaf(s_w[i],     v0, acc);
            acc = fmaf(s_w[i + 1], v1, acc);
            acc = fmaf(s_w[i + 2], v2, acc);
            acc = fmaf(s_w[i + 3], v3, acc);
            acc = fmaf(s_w[i + 4], v4, acc);
            acc = fmaf(s_w[i + 5], v5, acc);
            acc = fmaf(s_w[i + 6], v6, acc);
            acc = fmaf(s_w[i + 7], v7, acc);
        }
        for (; i < cnt; i++)
            acc = fmaf(s_w[i], H[(size_t)s_r[i] * FOUT + ch], acc);
        __syncthreads();
    }

    float self = H[(size_t)n * FOUT + ch];
    Aout[(size_t)n * FOUT + ch] = fmaf(dc, acc, fmaf(dc * dc, self, bias[ch]));
}

// ---------------- launch ------------------------------------------------------
extern "C" void kernel_launch(void* const* d_in, const int* in_sizes, int n_in,
                              void* d_out, int out_size)
{
    // identify inputs by element count (ordering-proof; all counts distinct)
    const float* x  = nullptr; const void* ei = nullptr;
    const float* W1 = nullptr; const float* b1 = nullptr;
    const float* W2 = nullptr; const float* b2 = nullptr;
    for (int i = 0; i < n_in; i++) {
        switch (in_sizes[i]) {
            case N_NODES * IN_C:   x  = (const float*)d_in[i]; break;
            case 2 * N_EDGES:      ei = d_in[i];               break;
            case IN_C * HID_C:     W1 = (const float*)d_in[i]; break;
            case HID_C:            b1 = (const float*)d_in[i]; break;
            case HID_C * OUT_C:    W2 = (const float*)d_in[i]; break;
            case OUT_C:            b2 = (const float*)d_in[i]; break;
            default: break;
        }
    }
    float* out = (float*)d_out;

    // edge normalization + degree histogram (fused) + CSR build
    detect_kernel<<<1, 1>>>((const unsigned int*)ei);
    zero_cnt_kernel<<<(N_NODES + 255) / 256, 256>>>();
    convert_hist_kernel<<<(N_EDGES + 255) / 256, 256>>>(ei);
    scan1_kernel<<<NB1, SCAN_BLK>>>();
    scan2_kernel<<<1, 256>>>();
    scan3_kernel<<<(N_NODES + 255) / 256, 256>>>();
    csr_fill_kernel<<<(N_EDGES + 255) / 256, 256>>>();

    // layer 1: h1 = x@W1 ; a1 = gather(h1) + self + b1
    gemm_kernel<1><<<(N_NODES + 63) / 64, 256>>>(x, W1);
    float* p_a1; cudaGetSymbolAddress((void**)&p_a1, g_a1);
    float* p_h1; cudaGetSymbolAddress((void**)&p_h1, g_h1);
    gather_kernel<HID_C><<<N_NODES, HID_C>>>(p_h1, b1, p_a1);

    // layer 2: h2 = relu(a1)@W2 ; out = gather(h2) + self + b2 (direct to d_out)
    gemm_kernel<2><<<(N_NODES + 63) / 64, 256>>>(nullptr, W2);
    float* p_h2; cudaGetSymbolAddress((void**)&p_h2, g_h2);
    gather_kernel<OUT_C><<<N_NODES, OUT_C>>>(p_h2, b2, out);
}

// round 9
// speedup vs baseline: 2.3378x; 1.1931x over previous
#include <cuda_runtime.h>
#include <cuda_bf16.h>
#include <math.h>

#define N_NODES 100000
#define IN_C 128
#define HID_C 128
#define OUT_C 64
#define N_EDGES 1600000

#define SCAN_BLK 512
#define NB1 ((N_NODES + SCAN_BLK - 1) / SCAN_BLK)   // 196

// ---------------- scratch (device globals: no allocations allowed) ----------
__device__ __align__(16) float g_dinv[N_NODES];
__device__ __align__(16) float g_h1[(size_t)N_NODES * HID_C];   // x @ W1 (raw)
__device__ __align__(16) float g_a1[(size_t)N_NODES * HID_C];   // layer-1 output (pre-relu)
__device__ __align__(16) float g_h2[(size_t)N_NODES * OUT_C];   // relu(a1) @ W2 (raw)
__device__ __align__(16) int2  g_rc[N_EDGES];        // packed {row, col}
__device__ __align__(16) int2  g_csre[N_EDGES];      // packed {row, bits(dinv[row])}
__device__ __align__(16) int   g_cnt[N_NODES];       // per-col degree (no self-loop)
__device__ __align__(16) int   g_incl[N_NODES];      // inclusive scan within block
__device__ __align__(16) int   g_part[256];          // block partial sums
__device__ __align__(16) int   g_partoff[256];       // exclusive block offsets
__device__ __align__(16) int   g_ptr[N_NODES + 1];   // CSR pointers (by col)
__device__ __align__(16) int   g_cur[N_NODES];       // fill cursors
__device__ int g_is64;

// ---------------- f32x2 packed-FMA helpers ------------------------------------
__device__ __forceinline__ unsigned long long pack_dup(float x) {
    unsigned long long r;
    asm("mov.b64 %0, {%1, %1};" : "=l"(r) : "f"(x));
    return r;
}
__device__ __forceinline__ void fma2(unsigned long long& d,
                                     unsigned long long a, unsigned long long b) {
    asm("fma.rn.f32x2 %0, %1, %2, %0;" : "+l"(d) : "l"(a), "l"(b));
}
__device__ __forceinline__ void unpack2(unsigned long long v, float& lo, float& hi) {
    asm("mov.b64 {%0, %1}, %2;" : "=f"(lo), "=f"(hi) : "l"(v));
}

// ---------------- edge-index dtype detection (parallel) -----------------------
// int64 layout: odd 32-bit words all zero (indices < 2^17). 32 threads, ballot.
__global__ void detect_kernel(const unsigned int* __restrict__ ei32) {
    int t = threadIdx.x;
    unsigned nz = (ei32[2 * t + 1] != 0u) ? 1u : 0u;
    unsigned m = __ballot_sync(0xffffffffu, nz);
    if (t == 0) g_is64 = (m == 0u) ? 1 : 0;
}

__global__ void zero_cnt_kernel() {
    int i = blockIdx.x * blockDim.x + threadIdx.x;
    if (i < N_NODES) g_cnt[i] = 0;
}

// fused: decode -> clamp -> store packed {r,c} -> degree histogram
__global__ void convert_hist_kernel(const void* __restrict__ ei) {
    int e = blockIdx.x * blockDim.x + threadIdx.x;
    if (e >= N_EDGES) return;
    int r, c;
    if (g_is64) {
        const long long* p = (const long long*)ei;
        r = (int)p[e];
        c = (int)p[N_EDGES + e];
    } else {
        const int* p = (const int*)ei;
        r = p[e];
        c = p[N_EDGES + e];
    }
    r = min(max(r, 0), N_NODES - 1);
    c = min(max(c, 0), N_NODES - 1);
    g_rc[e] = make_int2(r, c);
    atomicAdd(&g_cnt[c], 1);
}

// ---------------- prefix scan + CSR fill --------------------------------------
__global__ __launch_bounds__(SCAN_BLK) void scan1_kernel() {
    __shared__ int s[SCAN_BLK];
    int t = threadIdx.x;
    int i = blockIdx.x * SCAN_BLK + t;
    int v = (i < N_NODES) ? g_cnt[i] : 0;
    s[t] = v;
    __syncthreads();
    for (int off = 1; off < SCAN_BLK; off <<= 1) {
        int add = (t >= off) ? s[t - off] : 0;
        __syncthreads();
        s[t] += add;
        __syncthreads();
    }
    if (i < N_NODES) g_incl[i] = s[t];
    if (t == SCAN_BLK - 1) g_part[blockIdx.x] = s[t];
}

__global__ __launch_bounds__(256) void scan2_kernel() {
    __shared__ int s[256];
    int t = threadIdx.x;
    int v = (t < NB1) ? g_part[t] : 0;
    s[t] = v;
    __syncthreads();
    for (int off = 1; off < 256; off <<= 1) {
        int add = (t >= off) ? s[t - off] : 0;
        __syncthreads();
        s[t] += add;
        __syncthreads();
    }
    g_partoff[t] = s[t] - v;   // exclusive
}

__global__ void scan3_kernel() {
    int i = blockIdx.x * blockDim.x + threadIdx.x;
    if (i >= N_NODES) return;
    int cnt  = g_cnt[i];
    int excl = g_partoff[i / SCAN_BLK] + g_incl[i] - cnt;
    g_ptr[i] = excl;
    g_cur[i] = excl;
    g_dinv[i] = rsqrtf((float)cnt + 1.0f);
    if (i == 0) g_ptr[N_NODES] = N_EDGES;
}

__global__ void csr_fill_kernel() {
    int e = blockIdx.x * blockDim.x + threadIdx.x;
    if (e >= N_EDGES) return;
    int2 rc = g_rc[e];
    int pos = atomicAdd(&g_cur[rc.y], 1);
    g_csre[pos] = make_int2(rc.x, __float_as_int(g_dinv[rc.x]));
}

// ---------------- GEMM: H = (relu?)X @ W, f32x2 packed FMA --------------------
template <int LAYER>
__global__ __launch_bounds__(256) void gemm_kernel(
    const float* __restrict__ X,       // used only for LAYER==1
    const float* __restrict__ W)
{
    constexpr int FIN   = 128;
    constexpr int FOUT  = (LAYER == 1) ? HID_C : OUT_C;
    constexpr int NTILE = 64;
    constexpr int KSTEP = 32;
    constexpr int CH    = (FOUT * NTILE) / (256 * 4);  // 8 / 4
    constexpr int PAIRS = CH / 2;                      // 4 / 2
    constexpr int PITCH = NTILE + 1;

    __shared__ float sW[KSTEP * FOUT];
    __shared__ float sXT[KSTEP * PITCH];

    const int tid = threadIdx.x;
    const int n0  = blockIdx.x * NTILE;

    const int cg = tid % (FOUT / CH);
    const int ng = tid / (FOUT / CH);
    const int j0 = cg * CH;
    const int m0 = ng * 4;

    unsigned long long acc2[4][PAIRS];
    #pragma unroll
    for (int a = 0; a < 4; a++)
        #pragma unroll
        for (int b = 0; b < PAIRS; b++) acc2[a][b] = 0ULL;

    for (int k0 = 0; k0 < FIN; k0 += KSTEP) {
        __syncthreads();
        {
            const float4* W4  = (const float4*)(W + (size_t)k0 * FOUT);
            float4*       sW4 = (float4*)sW;
            constexpr int CNT = KSTEP * FOUT / 4;
            #pragma unroll
            for (int i = tid; i < CNT; i += 256) sW4[i] = W4[i];
        }
        {
            constexpr int CNT = KSTEP * NTILE;
            #pragma unroll
            for (int i = tid; i < CNT; i += 256) {
                int k = i % KSTEP;
                int m = i / KSTEP;
                int n = n0 + m;
                float v = 0.0f;
                if (n < N_NODES) {
                    if (LAYER == 1) {
                        v = X[(size_t)n * FIN + k0 + k];
                    } else {
                        v = fmaxf(g_a1[(size_t)n * FIN + k0 + k], 0.0f);
                    }
                }
                sXT[k * PITCH + m] = v;
            }
        }
        __syncthreads();

        #pragma unroll 8
        for (int k = 0; k < KSTEP; k++) {
            unsigned long long w2[PAIRS];
            #pragma unroll
            for (int p = 0; p < PAIRS; p++)
                w2[p] = *(const unsigned long long*)&sW[k * FOUT + j0 + 2 * p];
            unsigned long long xp[4];
            #pragma unroll
            for (int mi = 0; mi < 4; mi++)
                xp[mi] = pack_dup(sXT[k * PITCH + m0 + mi]);
            #pragma unroll
            for (int mi = 0; mi < 4; mi++)
                #pragma unroll
                for (int p = 0; p < PAIRS; p++)
                    fma2(acc2[mi][p], xp[mi], w2[p]);
        }
    }

    float* Hout = (LAYER == 1) ? g_h1 : g_h2;
    #pragma unroll
    for (int mi = 0; mi < 4; mi++) {
        int n = n0 + m0 + mi;
        if (n < N_NODES) {
            #pragma unroll
            for (int p = 0; p < PAIRS; p += 2) {
                float4 hv;
                unpack2(acc2[mi][p],     hv.x, hv.y);
                unpack2(acc2[mi][p + 1], hv.z, hv.w);
                *(float4*)&Hout[(size_t)n * FOUT + j0 + 2 * p] = hv;
            }
        }
    }
}

// ---------------- CSR gather: one WARP per destination node -------------------
// agg[c] = dinv[c] * sum_j dinv[r_j] * H[r_j]  +  dinv[c]^2 * H[c]  +  bias
// Metadata: one int2 per lane, broadcast via shfl (no smem, no bar.sync).
// Row loads: LDG.128 (FOUT=128) / LDG.64 (FOUT=64) per lane, 512B/256B per warp.
template <int FOUT>
__global__ __launch_bounds__(256) void gather_kernel(
    const float* __restrict__ H,
    const float* __restrict__ bias,
    float* __restrict__ Aout)
{
    constexpr int VEC = FOUT / 32;   // 4 or 2 floats per lane
    const int node = (blockIdx.x * 256 + threadIdx.x) >> 5;
    const int lane = threadIdx.x & 31;
    if (node >= N_NODES) return;

    const int beg = g_ptr[node];
    const int end = g_ptr[node + 1];
    const float dc = g_dinv[node];

    float acc[VEC];
    #pragma unroll
    for (int v = 0; v < VEC; v++) acc[v] = 0.0f;

    for (int base = beg; base < end; base += 32) {
        int j = base + lane;
        int2 meta = (j < end) ? g_csre[j] : make_int2(0, 0);
        int cnt = min(32, end - base);
        #pragma unroll 4
        for (int i = 0; i < cnt; i++) {
            int   r = __shfl_sync(0xffffffffu, meta.x, i);
            float w = __int_as_float(__shfl_sync(0xffffffffu, meta.y, i));
            const float* row = H + (size_t)r * FOUT + lane * VEC;
            if (VEC == 4) {
                float4 v = *(const float4*)row;
                acc[0] = fmaf(w, v.x, acc[0]);
                acc[1] = fmaf(w, v.y, acc[1]);
                acc[2] = fmaf(w, v.z, acc[2]);
                acc[3] = fmaf(w, v.w, acc[3]);
            } else {
                float2 v = *(const float2*)row;
                acc[0] = fmaf(w, v.x, acc[0]);
                acc[1] = fmaf(w, v.y, acc[1]);
            }
        }
    }

    const float d2 = dc * dc;
    const float* srow = H + (size_t)node * FOUT + lane * VEC;
    float* orow = Aout + (size_t)node * FOUT + lane * VEC;
    if (VEC == 4) {
        float4 s = *(const float4*)srow;
        const float4 b = *(const float4*)(bias + lane * 4);
        float4 o;
        o.x = fmaf(dc, acc[0], fmaf(d2, s.x, b.x));
        o.y = fmaf(dc, acc[1], fmaf(d2, s.y, b.y));
        o.z = fmaf(dc, acc[2], fmaf(d2, s.z, b.z));
        o.w = fmaf(dc, acc[3], fmaf(d2, s.w, b.w));
        *(float4*)orow = o;
    } else {
        float2 s = *(const float2*)srow;
        const float2 b = *(const float2*)(bias + lane * 2);
        float2 o;
        o.x = fmaf(dc, acc[0], fmaf(d2, s.x, b.x));
        o.y = fmaf(dc, acc[1], fmaf(d2, s.y, b.y));
        *(float2*)orow = o;
    }
}

// ---------------- launch ------------------------------------------------------
extern "C" void kernel_launch(void* const* d_in, const int* in_sizes, int n_in,
                              void* d_out, int out_size)
{
    // identify inputs by element count (ordering-proof; all counts distinct)
    const float* x  = nullptr; const void* ei = nullptr;
    const float* W1 = nullptr; const float* b1 = nullptr;
    const float* W2 = nullptr; const float* b2 = nullptr;
    for (int i = 0; i < n_in; i++) {
        switch (in_sizes[i]) {
            case N_NODES * IN_C:   x  = (const float*)d_in[i]; break;
            case 2 * N_EDGES:      ei = d_in[i];               break;
            case IN_C * HID_C:     W1 = (const float*)d_in[i]; break;
            case HID_C:            b1 = (const float*)d_in[i]; break;
            case HID_C * OUT_C:    W2 = (const float*)d_in[i]; break;
            case OUT_C:            b2 = (const float*)d_in[i]; break;
            default: break;
        }
    }
    float* out = (float*)d_out;

    // edge normalization + degree histogram (fused) + CSR build
    detect_kernel<<<1, 32>>>((const unsigned int*)ei);
    zero_cnt_kernel<<<(N_NODES + 255) / 256, 256>>>();
    convert_hist_kernel<<<(N_EDGES + 255) / 256, 256>>>(ei);
    scan1_kernel<<<NB1, SCAN_BLK>>>();
    scan2_kernel<<<1, 256>>>();
    scan3_kernel<<<(N_NODES + 255) / 256, 256>>>();
    csr_fill_kernel<<<(N_EDGES + 255) / 256, 256>>>();

    // layer 1: h1 = x@W1 ; a1 = gather(h1) + self + b1
    gemm_kernel<1><<<(N_NODES + 63) / 64, 256>>>(x, W1);
    float* p_a1; cudaGetSymbolAddress((void**)&p_a1, g_a1);
    float* p_h1; cudaGetSymbolAddress((void**)&p_h1, g_h1);
    gather_kernel<HID_C><<<(N_NODES * 32 + 255) / 256, 256>>>(p_h1, b1, p_a1);

    // layer 2: h2 = relu(a1)@W2 ; out = gather(h2) + self + b2 (direct to d_out)
    gemm_kernel<2><<<(N_NODES + 63) / 64, 256>>>(nullptr, W2);
    float* p_h2; cudaGetSymbolAddress((void**)&p_h2, g_h2);
    gather_kernel<OUT_C><<<(N_NODES * 32 + 255) / 256, 256>>>(p_h2, b2, out);
}

// round 10
// speedup vs baseline: 2.4243x; 1.0370x over previous
#include <cuda_runtime.h>
#include <cuda_fp16.h>
#include <math.h>

#define N_NODES 100000
#define IN_C 128
#define HID_C 128
#define OUT_C 64
#define N_EDGES 1600000

#define SCAN_BLK 512
#define NB1 ((N_NODES + SCAN_BLK - 1) / SCAN_BLK)   // 196

// ---------------- scratch (device globals: no allocations allowed) ----------
__device__ __align__(16) float  g_dinv[N_NODES];
__device__ __align__(16) __half g_h1[(size_t)N_NODES * HID_C];  // x @ W1 (fp16)
__device__ __align__(16) __half g_a1[(size_t)N_NODES * HID_C];  // layer-1 out (fp16)
__device__ __align__(16) __half g_h2[(size_t)N_NODES * OUT_C];  // relu(a1) @ W2 (fp16)
__device__ __align__(16) int2   g_csre[N_EDGES];     // packed {row, bits(dinv[row])}
__device__ __align__(16) int    g_cnt[N_NODES];      // per-col degree (no self-loop)
__device__ __align__(16) int    g_incl[N_NODES];     // inclusive scan within block
__device__ __align__(16) int    g_part[256];         // block partial sums
__device__ __align__(16) int    g_partoff[256];      // exclusive block offsets
__device__ __align__(16) int    g_ptr[N_NODES + 1];  // CSR pointers (by col)
__device__ __align__(16) int    g_cur[N_NODES];      // fill cursors
__device__ int g_is64;

// ---------------- f32x2 packed-FMA helpers ------------------------------------
__device__ __forceinline__ unsigned long long pack_dup(float x) {
    unsigned long long r;
    asm("mov.b64 %0, {%1, %1};" : "=l"(r) : "f"(x));
    return r;
}
__device__ __forceinline__ void fma2(unsigned long long& d,
                                     unsigned long long a, unsigned long long b) {
    asm("fma.rn.f32x2 %0, %1, %2, %0;" : "+l"(d) : "l"(a), "l"(b));
}
__device__ __forceinline__ void unpack2(unsigned long long v, float& lo, float& hi) {
    asm("mov.b64 {%0, %1}, %2;" : "=f"(lo), "=f"(hi) : "l"(v));
}

// ---------------- edge decode (shared by hist + fill) --------------------------
__device__ __forceinline__ void decode_edge(const void* __restrict__ ei, int e,
                                            int& r, int& c) {
    if (g_is64) {
        const long long* p = (const long long*)ei;
        r = (int)p[e];
        c = (int)p[N_EDGES + e];
    } else {
        const int* p = (const int*)ei;
        r = p[e];
        c = p[N_EDGES + e];
    }
    r = min(max(r, 0), N_NODES - 1);
    c = min(max(c, 0), N_NODES - 1);
}

// int64 layout: odd 32-bit words all zero (indices < 2^17). 32 threads, ballot.
__global__ void detect_kernel(const unsigned int* __restrict__ ei32) {
    int t = threadIdx.x;
    unsigned nz = (ei32[2 * t + 1] != 0u) ? 1u : 0u;
    unsigned m = __ballot_sync(0xffffffffu, nz);
    if (t == 0) g_is64 = (m == 0u) ? 1 : 0;
}

__global__ void zero_cnt_kernel() {
    int i = blockIdx.x * blockDim.x + threadIdx.x;
    if (i < N_NODES) g_cnt[i] = 0;
}

__global__ void hist_kernel(const void* __restrict__ ei) {
    int e = blockIdx.x * blockDim.x + threadIdx.x;
    if (e >= N_EDGES) return;
    int r, c;
    decode_edge(ei, e, r, c);
    atomicAdd(&g_cnt[c], 1);
}

// ---------------- prefix scan + CSR fill --------------------------------------
__global__ __launch_bounds__(SCAN_BLK) void scan1_kernel() {
    __shared__ int s[SCAN_BLK];
    int t = threadIdx.x;
    int i = blockIdx.x * SCAN_BLK + t;
    int v = (i < N_NODES) ? g_cnt[i] : 0;
    s[t] = v;
    __syncthreads();
    for (int off = 1; off < SCAN_BLK; off <<= 1) {
        int add = (t >= off) ? s[t - off] : 0;
        __syncthreads();
        s[t] += add;
        __syncthreads();
    }
    if (i < N_NODES) g_incl[i] = s[t];
    if (t == SCAN_BLK - 1) g_part[blockIdx.x] = s[t];
}

__global__ __launch_bounds__(256) void scan2_kernel() {
    __shared__ int s[256];
    int t = threadIdx.x;
    int v = (t < NB1) ? g_part[t] : 0;
    s[t] = v;
    __syncthreads();
    for (int off = 1; off < 256; off <<= 1) {
        int add = (t >= off) ? s[t - off] : 0;
        __syncthreads();
        s[t] += add;
        __syncthreads();
    }
    g_partoff[t] = s[t] - v;   // exclusive
}

__global__ void scan3_kernel() {
    int i = blockIdx.x * blockDim.x + threadIdx.x;
    if (i >= N_NODES) return;
    int cnt  = g_cnt[i];
    int excl = g_partoff[i / SCAN_BLK] + g_incl[i] - cnt;
    g_ptr[i] = excl;
    g_cur[i] = excl;
    g_dinv[i] = rsqrtf((float)cnt + 1.0f);
    if (i == 0) g_ptr[N_NODES] = N_EDGES;
}

__global__ void csr_fill_kernel(const void* __restrict__ ei) {
    int e = blockIdx.x * blockDim.x + threadIdx.x;
    if (e >= N_EDGES) return;
    int r, c;
    decode_edge(ei, e, r, c);
    int pos = atomicAdd(&g_cur[c], 1);
    g_csre[pos] = make_int2(r, __float_as_int(g_dinv[r]));
}

// ---------------- GEMM: H = (relu?)X @ W, f32x2 FMA, fp16 output --------------
template <int LAYER>
__global__ __launch_bounds__(256) void gemm_kernel(
    const float* __restrict__ X,       // used only for LAYER==1
    const float* __restrict__ W)
{
    constexpr int FIN   = 128;
    constexpr int FOUT  = (LAYER == 1) ? HID_C : OUT_C;
    constexpr int NTILE = 64;
    constexpr int KSTEP = 32;
    constexpr int CH    = (FOUT * NTILE) / (256 * 4);  // 8 / 4
    constexpr int PAIRS = CH / 2;                      // 4 / 2
    constexpr int PITCH = NTILE + 1;

    __shared__ float sW[KSTEP * FOUT];
    __shared__ float sXT[KSTEP * PITCH];

    const int tid = threadIdx.x;
    const int n0  = blockIdx.x * NTILE;

    const int cg = tid % (FOUT / CH);
    const int ng = tid / (FOUT / CH);
    const int j0 = cg * CH;
    const int m0 = ng * 4;

    unsigned long long acc2[4][PAIRS];
    #pragma unroll
    for (int a = 0; a < 4; a++)
        #pragma unroll
        for (int b = 0; b < PAIRS; b++) acc2[a][b] = 0ULL;

    for (int k0 = 0; k0 < FIN; k0 += KSTEP) {
        __syncthreads();
        {
            const float4* W4  = (const float4*)(W + (size_t)k0 * FOUT);
            float4*       sW4 = (float4*)sW;
            constexpr int CNT = KSTEP * FOUT / 4;
            #pragma unroll
            for (int i = tid; i < CNT; i += 256) sW4[i] = W4[i];
        }
        {
            constexpr int CNT = KSTEP * NTILE;
            #pragma unroll
            for (int i = tid; i < CNT; i += 256) {
                int k = i % KSTEP;
                int m = i / KSTEP;
                int n = n0 + m;
                float v = 0.0f;
                if (n < N_NODES) {
                    if (LAYER == 1) {
                        v = X[(size_t)n * FIN + k0 + k];
                    } else {
                        v = fmaxf(__half2float(g_a1[(size_t)n * FIN + k0 + k]), 0.0f);
                    }
                }
                sXT[k * PITCH + m] = v;
            }
        }
        __syncthreads();

        #pragma unroll 8
        for (int k = 0; k < KSTEP; k++) {
            unsigned long long w2[PAIRS];
            #pragma unroll
            for (int p = 0; p < PAIRS; p++)
                w2[p] = *(const unsigned long long*)&sW[k * FOUT + j0 + 2 * p];
            unsigned long long xp[4];
            #pragma unroll
            for (int mi = 0; mi < 4; mi++)
                xp[mi] = pack_dup(sXT[k * PITCH + m0 + mi]);
            #pragma unroll
            for (int mi = 0; mi < 4; mi++)
                #pragma unroll
                for (int p = 0; p < PAIRS; p++)
                    fma2(acc2[mi][p], xp[mi], w2[p]);
        }
    }

    __half* Hout = (LAYER == 1) ? g_h1 : g_h2;
    #pragma unroll
    for (int mi = 0; mi < 4; mi++) {
        int n = n0 + m0 + mi;
        if (n < N_NODES) {
            #pragma unroll
            for (int p = 0; p < PAIRS; p++) {
                float lo, hi;
                unpack2(acc2[mi][p], lo, hi);
                __half2 h2v = __floats2half2_rn(lo, hi);
                *(__half2*)&Hout[(size_t)n * FOUT + j0 + 2 * p] = h2v;
            }
        }
    }
}

// ---------------- CSR gather: one WARP per destination node -------------------
// agg[c] = dinv[c] * sum_j dinv[r_j] * H[r_j]  +  dinv[c]^2 * H[c]  +  bias
// fp16 rows: 256B (FOUT=128) / 128B (FOUT=64) per warp per edge.
template <int FOUT, bool OUT_HALF>
__global__ __launch_bounds__(256) void gather_kernel(
    const __half* __restrict__ H,
    const float* __restrict__ bias,
    void* __restrict__ Aout)
{
    constexpr int VEC = FOUT / 32;   // halves per lane: 4 or 2
    const int node = (blockIdx.x * 256 + threadIdx.x) >> 5;
    const int lane = threadIdx.x & 31;
    if (node >= N_NODES) return;

    const int beg = g_ptr[node];
    const int end = g_ptr[node + 1];
    const float dc = g_dinv[node];

    float acc[VEC];
    #pragma unroll
    for (int v = 0; v < VEC; v++) acc[v] = 0.0f;

    for (int base = beg; base < end; base += 32) {
        int j = base + lane;
        int2 meta = (j < end) ? g_csre[j] : make_int2(0, 0);
        int cnt = min(32, end - base);
        #pragma unroll 4
        for (int i = 0; i < cnt; i++) {
            int   r = __shfl_sync(0xffffffffu, meta.x, i);
            float w = __int_as_float(__shfl_sync(0xffffffffu, meta.y, i));
            const __half* row = H + (size_t)r * FOUT + lane * VEC;
            if (VEC == 4) {
                uint2 u = *(const uint2*)row;
                float2 f0 = __half22float2(*(const __half2*)&u.x);
                float2 f1 = __half22float2(*(const __half2*)&u.y);
                acc[0] = fmaf(w, f0.x, acc[0]);
                acc[1] = fmaf(w, f0.y, acc[1]);
                acc[2] = fmaf(w, f1.x, acc[2]);
                acc[3] = fmaf(w, f1.y, acc[3]);
            } else {
                unsigned u = *(const unsigned*)row;
                float2 f0 = __half22float2(*(const __half2*)&u);
                acc[0] = fmaf(w, f0.x, acc[0]);
                acc[1] = fmaf(w, f0.y, acc[1]);
            }
        }
    }

    const float d2 = dc * dc;
    const __half* srow = H + (size_t)node * FOUT + lane * VEC;
    float o[VEC];
    if (VEC == 4) {
        uint2 u = *(const uint2*)srow;
        float2 s0 = __half22float2(*(const __half2*)&u.x);
        float2 s1 = __half22float2(*(const __half2*)&u.y);
        const float4 b = *(const float4*)(bias + lane * 4);
        o[0] = fmaf(dc, acc[0], fmaf(d2, s0.x, b.x));
        o[1] = fmaf(dc, acc[1], fmaf(d2, s0.y, b.y));
        o[2] = fmaf(dc, acc[2], fmaf(d2, s1.x, b.z));
        o[3] = fmaf(dc, acc[3], fmaf(d2, s1.y, b.w));
    } else {
        unsigned u = *(const unsigned*)srow;
        float2 s0 = __half22float2(*(const __half2*)&u);
        const float2 b = *(const float2*)(bias + lane * 2);
        o[0] = fmaf(dc, acc[0], fmaf(d2, s0.x, b.x));
        o[1] = fmaf(dc, acc[1], fmaf(d2, s0.y, b.y));
    }

    if (OUT_HALF) {
        __half* orow = (__half*)Aout + (size_t)node * FOUT + lane * VEC;
        if (VEC == 4) {
            uint2 u;
            *(__half2*)&u.x = __floats2half2_rn(o[0], o[1]);
            *(__half2*)&u.y = __floats2half2_rn(o[2], o[3]);
            *(uint2*)orow = u;
        } else {
            *(__half2*)orow = __floats2half2_rn(o[0], o[1]);
        }
    } else {
        float* orow = (float*)Aout + (size_t)node * FOUT + lane * VEC;
        if (VEC == 4) {
            *(float4*)orow = make_float4(o[0], o[1], o[2], o[3]);
        } else {
            *(float2*)orow = make_float2(o[0], o[1]);
        }
    }
}

// ---------------- launch ------------------------------------------------------
extern "C" void kernel_launch(void* const* d_in, const int* in_sizes, int n_in,
                              void* d_out, int out_size)
{
    // identify inputs by element count (ordering-proof; all counts distinct)
    const float* x  = nullptr; const void* ei = nullptr;
    const float* W1 = nullptr; const float* b1 = nullptr;
    const float* W2 = nullptr; const float* b2 = nullptr;
    for (int i = 0; i < n_in; i++) {
        switch (in_sizes[i]) {
            case N_NODES * IN_C:   x  = (const float*)d_in[i]; break;
            case 2 * N_EDGES:      ei = d_in[i];               break;
            case IN_C * HID_C:     W1 = (const float*)d_in[i]; break;
            case HID_C:            b1 = (const float*)d_in[i]; break;
            case HID_C * OUT_C:    W2 = (const float*)d_in[i]; break;
            case OUT_C:            b2 = (const float*)d_in[i]; break;
            default: break;
        }
    }
    float* out = (float*)d_out;

    // edge histogram + CSR build (ei decoded twice, no staging array)
    detect_kernel<<<1, 32>>>((const unsigned int*)ei);
    zero_cnt_kernel<<<(N_NODES + 255) / 256, 256>>>();
    hist_kernel<<<(N_EDGES + 255) / 256, 256>>>(ei);
    scan1_kernel<<<NB1, SCAN_BLK>>>();
    scan2_kernel<<<1, 256>>>();
    scan3_kernel<<<(N_NODES + 255) / 256, 256>>>();
    csr_fill_kernel<<<(N_EDGES + 255) / 256, 256>>>(ei);

    __half* p_h1; cudaGetSymbolAddress((void**)&p_h1, g_h1);
    __half* p_a1; cudaGetSymbolAddress((void**)&p_a1, g_a1);
    __half* p_h2; cudaGetSymbolAddress((void**)&p_h2, g_h2);

    // layer 1: h1 = x@W1 (fp16) ; a1 = gather(h1) + self + b1 (fp16)
    gemm_kernel<1><<<(N_NODES + 63) / 64, 256>>>(x, W1);
    gather_kernel<HID_C, true><<<(N_NODES * 32 + 255) / 256, 256>>>(p_h1, b1, p_a1);

    // layer 2: h2 = relu(a1)@W2 (fp16) ; out = gather(h2) + self + b2 (fp32, direct)
    gemm_kernel<2><<<(N_NODES + 63) / 64, 256>>>(nullptr, W2);
    gather_kernel<OUT_C, false><<<(N_NODES * 32 + 255) / 256, 256>>>(p_h2, b2, out);
}

// round 11
// speedup vs baseline: 2.6811x; 1.1060x over previous
#include <cuda_runtime.h>
#include <cuda_fp16.h>
#include <math.h>

#define N_NODES 100000
#define IN_C 128
#define HID_C 128
#define OUT_C 64
#define N_EDGES 1600000

#define SCAN_BLK 512
#define NB1 ((N_NODES + SCAN_BLK - 1) / SCAN_BLK)   // 196

// ---------------- scratch (device globals: no allocations allowed) ----------
__device__ __align__(16) float  g_dinv[N_NODES];
__device__ __align__(16) __half g_h1[(size_t)N_NODES * HID_C];  // x @ W1 (fp16)
__device__ __align__(16) __half g_a1[(size_t)N_NODES * HID_C];  // layer-1 out (fp16)
__device__ __align__(16) __half g_h2[(size_t)N_NODES * OUT_C];  // relu(a1) @ W2 (fp16)
__device__ __align__(16) int2   g_csre[N_EDGES];     // packed {row, bits(dinv[row])}
__device__ __align__(16) int    g_cnt[N_NODES];      // per-col degree (no self-loop)
__device__ __align__(16) int    g_incl[N_NODES];     // inclusive scan within block
__device__ __align__(16) int    g_part[256];         // block partial sums
__device__ __align__(16) int    g_partoff[256];      // exclusive block offsets
__device__ __align__(16) int    g_ptr[N_NODES + 1];  // CSR pointers (by col)
__device__ __align__(16) int    g_cur[N_NODES];      // fill cursors
__device__ int g_is64;

// ---------------- f32x2 packed-FMA helpers ------------------------------------
__device__ __forceinline__ unsigned long long pack_dup(float x) {
    unsigned long long r;
    asm("mov.b64 %0, {%1, %1};" : "=l"(r) : "f"(x));
    return r;
}
__device__ __forceinline__ void fma2(unsigned long long& d,
                                     unsigned long long a, unsigned long long b) {
    asm("fma.rn.f32x2 %0, %1, %2, %0;" : "+l"(d) : "l"(a), "l"(b));
}
__device__ __forceinline__ void unpack2(unsigned long long v, float& lo, float& hi) {
    asm("mov.b64 {%0, %1}, %2;" : "=f"(lo), "=f"(hi) : "l"(v));
}

// ---------------- edge decode (shared by hist + fill) --------------------------
__device__ __forceinline__ void decode_edge(const void* __restrict__ ei, int e,
                                            int& r, int& c) {
    if (g_is64) {
        const long long* p = (const long long*)ei;
        r = (int)p[e];
        c = (int)p[N_EDGES + e];
    } else {
        const int* p = (const int*)ei;
        r = p[e];
        c = p[N_EDGES + e];
    }
    r = min(max(r, 0), N_NODES - 1);
    c = min(max(c, 0), N_NODES - 1);
}

// int64 layout: odd 32-bit words all zero (indices < 2^17). 32 threads, ballot.
__global__ void detect_kernel(const unsigned int* __restrict__ ei32) {
    int t = threadIdx.x;
    unsigned nz = (ei32[2 * t + 1] != 0u) ? 1u : 0u;
    unsigned m = __ballot_sync(0xffffffffu, nz);
    if (t == 0) g_is64 = (m == 0u) ? 1 : 0;
}

__global__ void zero_cnt_kernel() {
    int i = blockIdx.x * blockDim.x + threadIdx.x;
    if (i < N_NODES) g_cnt[i] = 0;
}

__global__ void hist_kernel(const void* __restrict__ ei) {
    int e = blockIdx.x * blockDim.x + threadIdx.x;
    if (e >= N_EDGES) return;
    int r, c;
    decode_edge(ei, e, r, c);
    atomicAdd(&g_cnt[c], 1);
}

// ---------------- prefix scan + CSR fill --------------------------------------
__global__ __launch_bounds__(SCAN_BLK) void scan1_kernel() {
    __shared__ int s[SCAN_BLK];
    int t = threadIdx.x;
    int i = blockIdx.x * SCAN_BLK + t;
    int v = (i < N_NODES) ? g_cnt[i] : 0;
    s[t] = v;
    __syncthreads();
    for (int off = 1; off < SCAN_BLK; off <<= 1) {
        int add = (t >= off) ? s[t - off] : 0;
        __syncthreads();
        s[t] += add;
        __syncthreads();
    }
    if (i < N_NODES) g_incl[i] = s[t];
    if (t == SCAN_BLK - 1) g_part[blockIdx.x] = s[t];
}

__global__ __launch_bounds__(256) void scan2_kernel() {
    __shared__ int s[256];
    int t = threadIdx.x;
    int v = (t < NB1) ? g_part[t] : 0;
    s[t] = v;
    __syncthreads();
    for (int off = 1; off < 256; off <<= 1) {
        int add = (t >= off) ? s[t - off] : 0;
        __syncthreads();
        s[t] += add;
        __syncthreads();
    }
    g_partoff[t] = s[t] - v;   // exclusive
}

__global__ void scan3_kernel() {
    int i = blockIdx.x * blockDim.x + threadIdx.x;
    if (i >= N_NODES) return;
    int cnt  = g_cnt[i];
    int excl = g_partoff[i / SCAN_BLK] + g_incl[i] - cnt;
    g_ptr[i] = excl;
    g_cur[i] = excl;
    g_dinv[i] = rsqrtf((float)cnt + 1.0f);
    if (i == 0) g_ptr[N_NODES] = N_EDGES;
}

__global__ void csr_fill_kernel(const void* __restrict__ ei) {
    int e = blockIdx.x * blockDim.x + threadIdx.x;
    if (e >= N_EDGES) return;
    int r, c;
    decode_edge(ei, e, r, c);
    int pos = atomicAdd(&g_cur[c], 1);
    g_csre[pos] = make_int2(r, __float_as_int(g_dinv[r]));
}

// ---------------- GEMM: H = (relu?)X @ W, f32x2 FMA, fp16 output --------------
template <int LAYER>
__global__ __launch_bounds__(256) void gemm_kernel(
    const float* __restrict__ X,       // used only for LAYER==1
    const float* __restrict__ W)
{
    constexpr int FIN   = 128;
    constexpr int FOUT  = (LAYER == 1) ? HID_C : OUT_C;
    constexpr int NTILE = 64;
    constexpr int KSTEP = 32;
    constexpr int CH    = (FOUT * NTILE) / (256 * 4);  // 8 / 4
    constexpr int PAIRS = CH / 2;                      // 4 / 2
    constexpr int PITCH = NTILE + 1;

    __shared__ float sW[KSTEP * FOUT];
    __shared__ float sXT[KSTEP * PITCH];

    const int tid = threadIdx.x;
    const int n0  = blockIdx.x * NTILE;

    const int cg = tid % (FOUT / CH);
    const int ng = tid / (FOUT / CH);
    const int j0 = cg * CH;
    const int m0 = ng * 4;

    unsigned long long acc2[4][PAIRS];
    #pragma unroll
    for (int a = 0; a < 4; a++)
        #pragma unroll
        for (int b = 0; b < PAIRS; b++) acc2[a][b] = 0ULL;

    for (int k0 = 0; k0 < FIN; k0 += KSTEP) {
        __syncthreads();
        {
            const float4* W4  = (const float4*)(W + (size_t)k0 * FOUT);
            float4*       sW4 = (float4*)sW;
            constexpr int CNT = KSTEP * FOUT / 4;
            #pragma unroll
            for (int i = tid; i < CNT; i += 256) sW4[i] = W4[i];
        }
        {
            constexpr int CNT = KSTEP * NTILE;
            #pragma unroll
            for (int i = tid; i < CNT; i += 256) {
                int k = i % KSTEP;
                int m = i / KSTEP;
                int n = n0 + m;
                float v = 0.0f;
                if (n < N_NODES) {
                    if (LAYER == 1) {
                        v = X[(size_t)n * FIN + k0 + k];
                    } else {
                        v = fmaxf(__half2float(g_a1[(size_t)n * FIN + k0 + k]), 0.0f);
                    }
                }
                sXT[k * PITCH + m] = v;
            }
        }
        __syncthreads();

        #pragma unroll 8
        for (int k = 0; k < KSTEP; k++) {
            unsigned long long w2[PAIRS];
            #pragma unroll
            for (int p = 0; p < PAIRS; p++)
                w2[p] = *(const unsigned long long*)&sW[k * FOUT + j0 + 2 * p];
            unsigned long long xp[4];
            #pragma unroll
            for (int mi = 0; mi < 4; mi++)
                xp[mi] = pack_dup(sXT[k * PITCH + m0 + mi]);
            #pragma unroll
            for (int mi = 0; mi < 4; mi++)
                #pragma unroll
                for (int p = 0; p < PAIRS; p++)
                    fma2(acc2[mi][p], xp[mi], w2[p]);
        }
    }

    __half* Hout = (LAYER == 1) ? g_h1 : g_h2;
    #pragma unroll
    for (int mi = 0; mi < 4; mi++) {
        int n = n0 + m0 + mi;
        if (n < N_NODES) {
            #pragma unroll
            for (int p = 0; p < PAIRS; p++) {
                float lo, hi;
                unpack2(acc2[mi][p], lo, hi);
                __half2 h2v = __floats2half2_rn(lo, hi);
                *(__half2*)&Hout[(size_t)n * FOUT + j0 + 2 * p] = h2v;
            }
        }
    }
}

// ---------------- CSR gather: one WARP per destination node -------------------
// agg[c] = dinv[c] * sum_j dinv[r_j] * H[r_j]  +  dinv[c]^2 * H[c]  +  bias
template <int FOUT, bool OUT_HALF>
__global__ __launch_bounds__(256) void gather_kernel(
    const __half* __restrict__ H,
    const float* __restrict__ bias,
    void* __restrict__ Aout)
{
    constexpr int VEC = FOUT / 32;   // halves per lane: 4 or 2
    const int node = (blockIdx.x * 256 + threadIdx.x) >> 5;
    const int lane = threadIdx.x & 31;
    if (node >= N_NODES) return;

    const int beg = g_ptr[node];
    const int end = g_ptr[node + 1];
    const float dc = g_dinv[node];

    float acc[VEC];
    #pragma unroll
    for (int v = 0; v < VEC; v++) acc[v] = 0.0f;

    for (int base = beg; base < end; base += 32) {
        int j = base + lane;
        int2 meta = (j < end) ? g_csre[j] : make_int2(0, 0);
        int cnt = min(32, end - base);
        #pragma unroll 8
        for (int i = 0; i < cnt; i++) {
            int   r = __shfl_sync(0xffffffffu, meta.x, i);
            float w = __int_as_float(__shfl_sync(0xffffffffu, meta.y, i));
            const __half* row = H + (size_t)r * FOUT + lane * VEC;
            if (VEC == 4) {
                uint2 u = *(const uint2*)row;
                float2 f0 = __half22float2(*(const __half2*)&u.x);
                float2 f1 = __half22float2(*(const __half2*)&u.y);
                acc[0] = fmaf(w, f0.x, acc[0]);
                acc[1] = fmaf(w, f0.y, acc[1]);
                acc[2] = fmaf(w, f1.x, acc[2]);
                acc[3] = fmaf(w, f1.y, acc[3]);
            } else {
                unsigned u = *(const unsigned*)row;
                float2 f0 = __half22float2(*(const __half2*)&u);
                acc[0] = fmaf(w, f0.x, acc[0]);
                acc[1] = fmaf(w, f0.y, acc[1]);
            }
        }
    }

    const float d2 = dc * dc;
    const __half* srow = H + (size_t)node * FOUT + lane * VEC;
    float o[VEC];
    if (VEC == 4) {
        uint2 u = *(const uint2*)srow;
        float2 s0 = __half22float2(*(const __half2*)&u.x);
        float2 s1 = __half22float2(*(const __half2*)&u.y);
        const float4 b = *(const float4*)(bias + lane * 4);
        o[0] = fmaf(dc, acc[0], fmaf(d2, s0.x, b.x));
        o[1] = fmaf(dc, acc[1], fmaf(d2, s0.y, b.y));
        o[2] = fmaf(dc, acc[2], fmaf(d2, s1.x, b.z));
        o[3] = fmaf(dc, acc[3], fmaf(d2, s1.y, b.w));
    } else {
        unsigned u = *(const unsigned*)srow;
        float2 s0 = __half22float2(*(const __half2*)&u);
        const float2 b = *(const float2*)(bias + lane * 2);
        o[0] = fmaf(dc, acc[0], fmaf(d2, s0.x, b.x));
        o[1] = fmaf(dc, acc[1], fmaf(d2, s0.y, b.y));
    }

    if (OUT_HALF) {
        __half* orow = (__half*)Aout + (size_t)node * FOUT + lane * VEC;
        if (VEC == 4) {
            uint2 u;
            *(__half2*)&u.x = __floats2half2_rn(o[0], o[1]);
            *(__half2*)&u.y = __floats2half2_rn(o[2], o[3]);
            *(uint2*)orow = u;
        } else {
            *(__half2*)orow = __floats2half2_rn(o[0], o[1]);
        }
    } else {
        float* orow = (float*)Aout + (size_t)node * FOUT + lane * VEC;
        if (VEC == 4) {
            *(float4*)orow = make_float4(o[0], o[1], o[2], o[3]);
        } else {
            *(float2*)orow = make_float2(o[0], o[1]);
        }
    }
}

// ---------------- launch ------------------------------------------------------
extern "C" void kernel_launch(void* const* d_in, const int* in_sizes, int n_in,
                              void* d_out, int out_size)
{
    // identify inputs by element count (ordering-proof; all counts distinct)
    const float* x  = nullptr; const void* ei = nullptr;
    const float* W1 = nullptr; const float* b1 = nullptr;
    const float* W2 = nullptr; const float* b2 = nullptr;
    for (int i = 0; i < n_in; i++) {
        switch (in_sizes[i]) {
            case N_NODES * IN_C:   x  = (const float*)d_in[i]; break;
            case 2 * N_EDGES:      ei = d_in[i];               break;
            case IN_C * HID_C:     W1 = (const float*)d_in[i]; break;
            case HID_C:            b1 = (const float*)d_in[i]; break;
            case HID_C * OUT_C:    W2 = (const float*)d_in[i]; break;
            case OUT_C:            b2 = (const float*)d_in[i]; break;
            default: break;
        }
    }
    float* out = (float*)d_out;

    __half* p_h1; cudaGetSymbolAddress((void**)&p_h1, g_h1);
    __half* p_a1; cudaGetSymbolAddress((void**)&p_a1, g_a1);
    __half* p_h2; cudaGetSymbolAddress((void**)&p_h2, g_h2);

    // side stream + fork/join events, created once (first call is uncaptured)
    static cudaStream_t s2 = nullptr;
    static cudaEvent_t ev_fork = nullptr, ev_join = nullptr;
    if (s2 == nullptr) {
        cudaStreamCreateWithFlags(&s2, cudaStreamNonBlocking);
        cudaEventCreateWithFlags(&ev_fork, cudaEventDisableTiming);
        cudaEventCreateWithFlags(&ev_join, cudaEventDisableTiming);
    }

    // ---- fork: CSR build on s2, GEMM1 on default stream (independent) ----
    cudaEventRecord(ev_fork, 0);
    cudaStreamWaitEvent(s2, ev_fork, 0);

    detect_kernel<<<1, 32, 0, s2>>>((const unsigned int*)ei);
    zero_cnt_kernel<<<(N_NODES + 255) / 256, 256, 0, s2>>>();
    hist_kernel<<<(N_EDGES + 255) / 256, 256, 0, s2>>>(ei);
    scan1_kernel<<<NB1, SCAN_BLK, 0, s2>>>();
    scan2_kernel<<<1, 256, 0, s2>>>();
    scan3_kernel<<<(N_NODES + 255) / 256, 256, 0, s2>>>();
    csr_fill_kernel<<<(N_EDGES + 255) / 256, 256, 0, s2>>>(ei);
    cudaEventRecord(ev_join, s2);

    gemm_kernel<1><<<(N_NODES + 63) / 64, 256>>>(x, W1);   // default stream

    // ---- join: gather1 needs both h1 (default) and CSR+dinv (s2) ----
    cudaStreamWaitEvent(0, ev_join, 0);

    gather_kernel<HID_C, true><<<(N_NODES * 32 + 255) / 256, 256>>>(p_h1, b1, p_a1);

    // layer 2: h2 = relu(a1)@W2 (fp16) ; out = gather(h2) + self + b2 (fp32)
    gemm_kernel<2><<<(N_NODES + 63) / 64, 256>>>(nullptr, W2);
    gather_kernel<OUT_C, false><<<(N_NODES * 32 + 255) / 256, 256>>>(p_h2, b2, out);
}